// round 8
// baseline (speedup 1.0000x reference)
#include <cuda_runtime.h>
#include <cstdint>

// Problem constants (fixed shapes per reference)
#define NSPANS 4096
#define TMAX   16
#define HDIM   768
#define H4     192          // HDIM / 4 (float4 lanes per row)
#define NPAIRS 16384
#define SL     2048         // S * L
#define NREPRB (NSPANS / 2) // 2048 repr blocks in kernel A

// Scratch: only the mean vectors [NSPANS, HDIM] = 12.6 MB.
__device__ float4 g_mean[NSPANS * H4];

// Output row layout (float4 units, 1152 total):
//   [ first_i(0..192) mean_i(192..384) last_i(384..576)
//     first_j(576..768) mean_j(768..960) last_j(960..1152) ]

// Kernel A: independent producer + first/last writer blocks in one grid.
//  bid <  NREPRB : repr producers (2 spans/block), write g_mean only.
//  bid >= NREPRB : pair first/last writers — offsets computed straight from
//                  span_doc/span_tok/span_len, NO dependency on producers.
__global__ __launch_bounds__(384) void kernelA(
    const float* __restrict__ hidden,
    const int*   __restrict__ span_doc,
    const int*   __restrict__ span_tok,
    const int*   __restrict__ span_len,
    const int*   __restrict__ pair_i,
    const int*   __restrict__ pair_j,
    float4*      __restrict__ out)
{
    const int bid = blockIdx.x;
    const int tid = threadIdx.x;

    if (bid < NREPRB) {
        // ---- repr/mean producer (R7-proven body) ----
        const int half = tid / H4;                // 0 or 1
        const int lane = tid - half * H4;         // 0..191
        const int n    = bid * 2 + half;

        __shared__ int s_tok[2][TMAX];
        if (lane < TMAX)
            s_tok[half][lane] = __ldg(span_tok + n * TMAX + lane);
        __syncthreads();

        const int doc   = __ldg(span_doc + n);
        const int len   = __ldg(span_len + n);    // 1..16
        const int lenm1 = len - 1;

        const float4* __restrict__ base =
            reinterpret_cast<const float4*>(hidden) + (size_t)doc * SL * H4;

        float4 acc = make_float4(0.f, 0.f, 0.f, 0.f);

        #pragma unroll
        for (int t = 0; t < TMAX; ++t) {
            const int tt = (t < len) ? t : lenm1;   // clamp -> L1-hit dup
            const float w = (t < len) ? 1.0f : 0.0f;
            const float4 v = __ldg(base + (size_t)s_tok[half][tt] * H4 + lane);
            acc.x += v.x * w; acc.y += v.y * w;
            acc.z += v.z * w; acc.w += v.w * w;
        }

        const float inv = 1.0f / (float)len;
        g_mean[n * H4 + lane] = make_float4(acc.x * inv, acc.y * inv,
                                            acc.z * inv, acc.w * inv);
        return;
    }

    // ---- first/last writer: 4 x 192 float4 per pair (2 per thread) ----
    const int p = bid - NREPRB;
    __shared__ int s_off[4];   // i_first, i_last, j_first, j_last (f4 units)

    if (tid == 0) {
        const int pi  = __ldg(pair_i + p);
        const int doc = __ldg(span_doc + pi);
        const int len = __ldg(span_len + pi);
        const int t0  = __ldg(span_tok + pi * TMAX);
        const int tl  = __ldg(span_tok + pi * TMAX + len - 1);
        s_off[0] = (doc * SL + t0) * H4;
        s_off[1] = (doc * SL + tl) * H4;
    } else if (tid == 32) {
        const int pj  = __ldg(pair_j + p);
        const int doc = __ldg(span_doc + pj);
        const int len = __ldg(span_len + pj);
        const int t0  = __ldg(span_tok + pj * TMAX);
        const int tl  = __ldg(span_tok + pj * TMAX + len - 1);
        s_off[2] = (doc * SL + t0) * H4;
        s_off[3] = (doc * SL + tl) * H4;
    }
    __syncthreads();

    const float4* __restrict__ hid4 = reinterpret_cast<const float4*>(hidden);
    float4* __restrict__ o = out + (size_t)p * 1152;

    const bool lo = (tid < 192);
    const int  t2 = tid - 192;

    const float4 v0 = lo ? __ldg(hid4 + s_off[0] + tid)   // first_i
                         : __ldg(hid4 + s_off[1] + t2);   // last_i
    const float4 v1 = lo ? __ldg(hid4 + s_off[2] + tid)   // first_j
                         : __ldg(hid4 + s_off[3] + t2);   // last_j

    __stcs(o + (lo ? tid : tid + 192),        v0);  // [0,192) / [384,576)
    __stcs(o + (lo ? 576 + tid : 960 + t2),   v1);  // [576,768) / [960,1152)
}

// Kernel B: mean chunks only — 2 x 192 float4 per pair (1 per thread).
__global__ __launch_bounds__(384) void kernelB(
    const int* __restrict__ pair_i,
    const int* __restrict__ pair_j,
    float4*    __restrict__ out)
{
    const int p   = blockIdx.x;
    const int tid = threadIdx.x;

    const bool lo = (tid < 192);
    const int  t2 = tid - 192;

    const int pi = __ldg(pair_i + p);
    const int pj = __ldg(pair_j + p);

    const float4 v = lo ? __ldg(g_mean + pi * H4 + tid)
                        : __ldg(g_mean + pj * H4 + t2);

    float4* __restrict__ o = out + (size_t)p * 1152;
    __stcs(o + (lo ? 192 + tid : 576 + tid), v);  // [192,384) / [768,960)
}

extern "C" void kernel_launch(void* const* d_in, const int* in_sizes, int n_in,
                              void* d_out, int out_size)
{
    const float* hidden   = (const float*)d_in[0];
    const int*   span_doc = (const int*)  d_in[1];
    const int*   span_tok = (const int*)  d_in[2];
    const int*   span_len = (const int*)  d_in[3];
    const int*   pair_i   = (const int*)  d_in[4];
    const int*   pair_j   = (const int*)  d_in[5];
    float4*      out      = (float4*)     d_out;

    kernelA<<<NREPRB + NPAIRS, 384>>>(hidden, span_doc, span_tok, span_len,
                                      pair_i, pair_j, out);
    kernelB<<<NPAIRS, 384>>>(pair_i, pair_j, out);
}

// round 9
// speedup vs baseline: 1.0809x; 1.0809x over previous
#include <cuda_runtime.h>
#include <cstdint>

// Problem constants (fixed shapes per reference)
#define NSPANS 4096
#define TMAX   16
#define HDIM   768
#define H4     192          // HDIM / 4 (float4 lanes per row)
#define NPAIRS 16384
#define SL     2048         // S * L

// Scratch: only the mean vectors [NSPANS, HDIM] = 12.6 MB.
// first/last are verbatim hidden rows -> re-gathered from L2 in kernel 2.
__device__ float4 g_mean[NSPANS * H4];
// Per-span {first_row_off, last_row_off} in float4 units into hidden.
__device__ int2 g_info[NSPANS];

// Kernel 1: 2 spans per block (384 threads: lanes 0-191 span A, 192-383 span B).
// Fixed fully-unrolled TMAX loop with clamped token index -> 16 independent
// loads in flight per thread (clamped duplicates are L1 hits, weight 0).
__global__ __launch_bounds__(384) void reprs_kernel(
    const float* __restrict__ hidden,
    const int*   __restrict__ span_doc,
    const int*   __restrict__ span_tok,
    const int*   __restrict__ span_len)
{
    const int tid  = threadIdx.x;
    const int half = tid / H4;                // 0 or 1
    const int lane = tid - half * H4;         // 0..191
    const int n    = blockIdx.x * 2 + half;

    __shared__ int s_tok[2][TMAX];
    if (lane < TMAX)
        s_tok[half][lane] = __ldg(span_tok + n * TMAX + lane);
    __syncthreads();

    const int doc   = __ldg(span_doc + n);
    const int len   = __ldg(span_len + n);    // 1..16
    const int lenm1 = len - 1;

    const float4* __restrict__ base =
        reinterpret_cast<const float4*>(hidden) + (size_t)doc * SL * H4;

    float4 acc = make_float4(0.f, 0.f, 0.f, 0.f);

    #pragma unroll
    for (int t = 0; t < TMAX; ++t) {
        const int tt = (t < len) ? t : lenm1;     // clamp -> L1-hit duplicate
        const float w = (t < len) ? 1.0f : 0.0f;
        const float4 v = __ldg(base + (size_t)s_tok[half][tt] * H4 + lane);
        acc.x += v.x * w; acc.y += v.y * w;
        acc.z += v.z * w; acc.w += v.w * w;
    }

    const float inv = 1.0f / (float)len;
    g_mean[n * H4 + lane] = make_float4(acc.x * inv, acc.y * inv,
                                        acc.z * inv, acc.w * inv);

    if (lane == 0) {
        const int docbase = doc * SL;
        g_info[n] = make_int2((docbase + s_tok[half][0]) * H4,
                              (docbase + s_tok[half][lenm1]) * H4);
    }
}

// Kernel 2: one block per pair, 384 threads, whole contiguous row per block.
// Output row layout (float4 units):
//   [ first_i(192) mean_i(192) last_i(192) first_j(192) mean_j(192) last_j(192) ]
// Thread tid covers lanes {tid, tid+384, tid+768}:
//   tid     : tid<192 -> first_i  else mean_i
//   tid+384 : tid<192 -> last_i   else first_j
//   tid+768 : tid<192 -> mean_j   else last_j
// first/last come straight from L2-resident hidden; mean from g_mean.
// All three loads issued first; stores are WRITE-THROUGH (__stwt) so output
// lines never allocate in L2 (output is never re-read) -> one LTS transaction
// per line instead of allocate+evict.
__global__ __launch_bounds__(384) void pairs_kernel(
    const float* __restrict__ hidden,
    const int*   __restrict__ pair_i,
    const int*   __restrict__ pair_j,
    float4*      __restrict__ out)
{
    const int p   = blockIdx.x;
    const int tid = threadIdx.x;
    const int pi  = __ldg(pair_i + p);
    const int pj  = __ldg(pair_j + p);

    const int2 ii = __ldg(&g_info[pi]);
    const int2 ij = __ldg(&g_info[pj]);

    const float4* __restrict__ hid4 = reinterpret_cast<const float4*>(hidden);
    float4* __restrict__ o = out + (size_t)p * 1152;

    const bool lo = (tid < 192);
    const int  t2 = tid - 192;

    const float4 v0 = lo ? __ldg(hid4 + ii.x + tid)
                         : __ldg(g_mean + pi * H4 + t2);
    const float4 v1 = lo ? __ldg(hid4 + ii.y + tid)
                         : __ldg(hid4 + ij.x + t2);
    const float4 v2 = lo ? __ldg(g_mean + pj * H4 + tid)
                         : __ldg(hid4 + ij.y + t2);

    __stwt(o + tid,       v0);
    __stwt(o + tid + 384, v1);
    __stwt(o + tid + 768, v2);
}

extern "C" void kernel_launch(void* const* d_in, const int* in_sizes, int n_in,
                              void* d_out, int out_size)
{
    const float* hidden   = (const float*)d_in[0];
    const int*   span_doc = (const int*)  d_in[1];
    const int*   span_tok = (const int*)  d_in[2];
    const int*   span_len = (const int*)  d_in[3];
    const int*   pair_i   = (const int*)  d_in[4];
    const int*   pair_j   = (const int*)  d_in[5];
    float4*      out      = (float4*)     d_out;

    reprs_kernel<<<NSPANS / 2, 384>>>(hidden, span_doc, span_tok, span_len);
    pairs_kernel<<<NPAIRS, 384>>>(hidden, pair_i, pair_j, out);
}